// round 5
// baseline (speedup 1.0000x reference)
#include <cuda_runtime.h>
#include <stdint.h>

// LayoutBBox: in (B,12,64) f32 -> out (B,8,128,128) f32
// out[b,c,h,w] = max_n xy[n,h,w]*cls[n,c], xy = max(lx(w)*gx(h), ly(h)*gy(w))
// Single fused kernel: per-CTA smem prep (records + exact bitmasks), then a
// divergent visit loop over exactly the nonzero boxes per pixel.

constexpr int Wd   = 128;
constexpr int Hd   = 128;
constexpr int NUMB = 64;
constexpr int NCLS = 8;
constexpr int INCH = 12;
constexpr int RPB  = 8;    // rows per CTA
constexpr int TY   = 4;    // blockDim.y; thread covers rows ty and ty+TY

using u64 = unsigned long long;

__device__ __forceinline__ u64 pk(float lo, float hi) {
    u64 r; asm("mov.b64 %0,{%1,%2};" : "=l"(r) : "f"(lo), "f"(hi)); return r;
}
__device__ __forceinline__ void upk(float& lo, float& hi, u64 v) {
    asm("mov.b64 {%0,%1},%2;" : "=f"(lo), "=f"(hi) : "l"(v));
}
__device__ __forceinline__ u64 pmul(u64 a, u64 b) {
    u64 r; asm("mul.rn.f32x2 %0,%1,%2;" : "=l"(r) : "l"(a), "l"(b)); return r;
}

__global__ __launch_bounds__(512, 3)
void layout_bbox_kernel(const float* __restrict__ in, float* __restrict__ out)
{
    __shared__ float4     sp[NUMB];        // x1, x2, y1, y2
    __shared__ ulonglong2 sca[NUMB];       // packed (c0,c1),(c2,c3)
    __shared__ ulonglong2 scb[NUMB];       // packed (c4,c5),(c6,c7)
    __shared__ ulonglong2 scm[Wd];         // (Mlx, Mgw) per w
    __shared__ ulonglong2 srm[RPB];        // (Mgh, Mly) per row

    const int tx  = threadIdx.x;           // w in [0,128)
    const int ty  = threadIdx.y;           // [0,4)
    const int tid = ty * Wd + tx;
    const int b   = blockIdx.y;
    const int hbase = blockIdx.x * RPB;

    // ---- stage 1: box records into smem (threads 0..63) ----
    if (tid < NUMB) {
        const float* base = in + (size_t)b * INCH * NUMB + tid;
        float xc = base[0 * NUMB] * 128.0f;
        float yc = base[1 * NUMB] * 128.0f;
        float bw = base[2 * NUMB] * 128.0f;
        float bh = base[3 * NUMB] * 128.0f;
        sp[tid] = make_float4(xc - 0.5f * bw, xc + 0.5f * bw,
                              yc - 0.5f * bh, yc + 0.5f * bh);
        ulonglong2 ca, cb;
        ca.x = pk(base[4 * NUMB],  base[5 * NUMB]);
        ca.y = pk(base[6 * NUMB],  base[7 * NUMB]);
        cb.x = pk(base[8 * NUMB],  base[9 * NUMB]);
        cb.y = pk(base[10 * NUMB], base[11 * NUMB]);
        sca[tid] = ca;
        scb[tid] = cb;
    }
    __syncthreads();

    // ---- stage 2: exact bitmasks, byte-parallel from smem params ----
    // column masks: 1024 (w, byte j) slots, 2 per thread
    #pragma unroll
    for (int s = tid; s < Wd * 8; s += Wd * TY) {
        int w = s >> 3, j = s & 7;
        float wf = (float)w;
        unsigned blx = 0, bgw = 0;
        #pragma unroll
        for (int k = 0; k < 8; k++) {
            float4 p = sp[8 * j + k];
            if (fabsf(wf - p.x) < 1.0f || fabsf(p.y - wf) < 1.0f) blx |= 1u << k;
            if (wf > p.x && wf < p.y)                             bgw |= 1u << k;
        }
        unsigned char* dst = (unsigned char*)&scm[w];
        dst[j]     = (unsigned char)blx;   // low u64 = Mlx
        dst[8 + j] = (unsigned char)bgw;   // high u64 = Mgw
    }
    // row masks: RPB*8 = 64 slots
    if (tid < RPB * 8) {
        int r = tid >> 3, j = tid & 7;
        float rf = (float)(hbase + r);
        unsigned bgh = 0, bly = 0;
        #pragma unroll
        for (int k = 0; k < 8; k++) {
            float4 p = sp[8 * j + k];
            if (rf > p.z && rf < p.w)                             bgh |= 1u << k;
            if (fabsf(rf - p.z) < 1.0f || fabsf(p.w - rf) < 1.0f) bly |= 1u << k;
        }
        unsigned char* dst = (unsigned char*)&srm[r];
        dst[j]     = (unsigned char)bgh;   // low u64 = Mgh
        dst[8 + j] = (unsigned char)bly;   // high u64 = Mly
    }
    __syncthreads();

    // ---- stage 3: visit exact nonzero boxes per pixel ----
    const ulonglong2 cm = scm[tx];
    const float wf = (float)tx;
    const int cs = Hd * Wd;

    #pragma unroll
    for (int pp = 0; pp < 2; pp++) {
        const int r = ty + pp * TY;
        const int h = hbase + r;
        const float hf = (float)h;
        const ulonglong2 rm = srm[r];
        u64 m = (cm.x & rm.x) | (cm.y & rm.y);   // exact nonzero-box set

        float a0 = 0.f, a1 = 0.f, a2 = 0.f, a3 = 0.f;
        float a4 = 0.f, a5 = 0.f, a6 = 0.f, a7 = 0.f;

        while (m) {                               // divergent per-lane loop
            int n = __ffsll((long long)m) - 1;
            m &= m - 1;
            float4 p = sp[n];                     // LDS.128
            float dx1 = wf - p.x, dx2 = p.y - wf;
            float dy1 = hf - p.z, dy2 = p.w - hf;
            float lx = fmaxf(0.0f, fmaxf(1.0f - fabsf(dx1), 1.0f - fabsf(dx2)));
            float gy = __saturatef(dx1) * __saturatef(dx2);
            float gx = __saturatef(dy1) * __saturatef(dy2);
            float ly = fmaxf(0.0f, fmaxf(1.0f - fabsf(dy1), 1.0f - fabsf(dy2)));
            float xy = fmaxf(lx * gx, ly * gy);

            u64 xyp = pk(xy, xy);
            ulonglong2 ca = sca[n];
            ulonglong2 cb = scb[n];
            float p0, p1;
            upk(p0, p1, pmul(xyp, ca.x)); a0 = fmaxf(a0, p0); a1 = fmaxf(a1, p1);
            upk(p0, p1, pmul(xyp, ca.y)); a2 = fmaxf(a2, p0); a3 = fmaxf(a3, p1);
            upk(p0, p1, pmul(xyp, cb.x)); a4 = fmaxf(a4, p0); a5 = fmaxf(a5, p1);
            upk(p0, p1, pmul(xyp, cb.y)); a6 = fmaxf(a6, p0); a7 = fmaxf(a7, p1);
        }

        float* o = out + (((size_t)b * NCLS) * Hd + h) * Wd + tx;
        o[0 * cs] = a0; o[1 * cs] = a1; o[2 * cs] = a2; o[3 * cs] = a3;
        o[4 * cs] = a4; o[5 * cs] = a5; o[6 * cs] = a6; o[7 * cs] = a7;
    }
}

extern "C" void kernel_launch(void* const* d_in, const int* in_sizes, int n_in,
                              void* d_out, int out_size)
{
    const float* in = (const float*)d_in[0];
    float* out = (float*)d_out;
    int B = in_sizes[0] / (INCH * NUMB);   // 16

    dim3 grid(Hd / RPB, B);    // (16, B) = 256 CTAs
    dim3 block(Wd, TY);        // 128 x 4 = 512 threads
    layout_bbox_kernel<<<grid, block>>>(in, out);
}

// round 6
// speedup vs baseline: 1.1261x; 1.1261x over previous
#include <cuda_runtime.h>
#include <stdint.h>

// LayoutBBox: in (B,12,64) f32 -> out (B,8,128,128) f32
// out[b,c,h,w] = max_n xy[n,h,w]*cls[n,c], xy = max(lx(w)*gx(h), ly(h)*gy(w))
// Kernel 1 (prep): exact per-(b,w)/(b,h) nonzero bitmasks + packed box records.
// Kernel 2 (main): 2 rows/thread, union-mask visit loop, record load + column
// profile amortized across both rows.

constexpr int Wd   = 128;
constexpr int Hd   = 128;
constexpr int NUMB = 64;
constexpr int NCLS = 8;
constexpr int INCH = 12;
constexpr int MAXB = 16;

using u64 = unsigned long long;

__device__ __forceinline__ u64 pk(float lo, float hi) {
    u64 r; asm("mov.b64 %0,{%1,%2};" : "=l"(r) : "f"(lo), "f"(hi)); return r;
}
__device__ __forceinline__ void upk(float& lo, float& hi, u64 v) {
    asm("mov.b64 {%0,%1},%2;" : "=f"(lo), "=f"(hi) : "l"(v));
}
__device__ __forceinline__ u64 pmul(u64 a, u64 b) {
    u64 r; asm("mul.rn.f32x2 %0,%1,%2;" : "=l"(r) : "l"(a), "l"(b)); return r;
}

struct __align__(16) Rec {              // 48 B per box
    float4     p;                       // x1, x2, y1, y2
    ulonglong2 ca;                      // packed (c0,c1),(c2,c3)
    ulonglong2 cb;                      // packed (c4,c5),(c6,c7)
};

__device__ ulonglong2 g_cmask[MAXB][Wd];   // (Mlx, Mgw) per (b,w)
__device__ ulonglong2 g_rmask[MAXB][Hd];   // (Mgh, Mly) per (b,h)
__device__ Rec        g_rec[MAXB][NUMB];

// ---------------- prep kernel: grid (2, B), block 1024 ----------------
__global__ void prep_kernel(const float* __restrict__ in)
{
    const int b   = blockIdx.y;
    const int tid = threadIdx.x;
    const float* base = in + (size_t)b * INCH * NUMB;

    if (blockIdx.x == 0) {
        if (tid < NUMB) {
            float xc = base[0 * NUMB + tid] * 128.0f;
            float yc = base[1 * NUMB + tid] * 128.0f;
            float bw = base[2 * NUMB + tid] * 128.0f;
            float bh = base[3 * NUMB + tid] * 128.0f;
            Rec r;
            r.p = make_float4(xc - 0.5f * bw, xc + 0.5f * bw,
                              yc - 0.5f * bh, yc + 0.5f * bh);
            r.ca.x = pk(base[4 * NUMB + tid],  base[5 * NUMB + tid]);
            r.ca.y = pk(base[6 * NUMB + tid],  base[7 * NUMB + tid]);
            r.cb.x = pk(base[8 * NUMB + tid],  base[9 * NUMB + tid]);
            r.cb.y = pk(base[10 * NUMB + tid], base[11 * NUMB + tid]);
            g_rec[b][tid] = r;
        }
        {   // column masks, byte-parallel
            int w = tid >> 3, j = tid & 7;
            float wf = (float)w;
            unsigned blx = 0, bgw = 0;
            #pragma unroll
            for (int k = 0; k < 8; k++) {
                int n = 8 * j + k;
                float xc = base[0 * NUMB + n] * 128.0f;
                float bw = base[2 * NUMB + n] * 128.0f;
                float x1 = xc - 0.5f * bw, x2 = xc + 0.5f * bw;
                if (fabsf(wf - x1) < 1.0f || fabsf(x2 - wf) < 1.0f) blx |= 1u << k;
                if (wf > x1 && wf < x2)                             bgw |= 1u << k;
            }
            unsigned char* dst = (unsigned char*)&g_cmask[b][w];
            dst[j]     = (unsigned char)blx;
            dst[8 + j] = (unsigned char)bgw;
        }
    } else {
        // row masks
        int h = tid >> 3, j = tid & 7;
        float hf = (float)h;
        unsigned bgh = 0, bly = 0;
        #pragma unroll
        for (int k = 0; k < 8; k++) {
            int n = 8 * j + k;
            float yc = base[1 * NUMB + n] * 128.0f;
            float bh = base[3 * NUMB + n] * 128.0f;
            float y1 = yc - 0.5f * bh, y2 = yc + 0.5f * bh;
            if (hf > y1 && hf < y2)                             bgh |= 1u << k;
            if (fabsf(hf - y1) < 1.0f || fabsf(y2 - hf) < 1.0f) bly |= 1u << k;
        }
        unsigned char* dst = (unsigned char*)&g_rmask[b][h];
        dst[j]     = (unsigned char)bgh;
        dst[8 + j] = (unsigned char)bly;
    }
}

// -------- main kernel: grid (Hd/4, B), block (128, 2); 2 rows/thread --------
__global__ __launch_bounds__(256)
void layout_bbox_main(float* __restrict__ out)
{
    const int tx = threadIdx.x;                       // w
    const int b  = blockIdx.y;
    const int h0 = blockIdx.x * 4 + threadIdx.y * 2;  // rows h0, h0+1
    const float wf  = (float)tx;
    const float hf0 = (float)h0;
    const float hf1 = hf0 + 1.0f;

    const ulonglong2 cm  = g_cmask[b][tx];
    const ulonglong2 rm0 = g_rmask[b][h0];
    const ulonglong2 rm1 = g_rmask[b][h0 + 1];
    // union of the two rows' exact nonzero-box sets
    u64 m = (cm.x & (rm0.x | rm1.x)) | (cm.y & (rm0.y | rm1.y));

    float a0 = 0.f, a1 = 0.f, a2 = 0.f, a3 = 0.f;
    float a4 = 0.f, a5 = 0.f, a6 = 0.f, a7 = 0.f;
    float b0 = 0.f, b1 = 0.f, b2 = 0.f, b3 = 0.f;
    float b4 = 0.f, b5 = 0.f, b6 = 0.f, b7 = 0.f;

    while (m) {
        int n = __ffsll((long long)m) - 1;
        m &= m - 1;
        Rec r = g_rec[b][n];                          // 3x LDG.128, L1-resident

        // column profile — shared by both rows
        float dx1 = wf - r.p.x, dx2 = r.p.y - wf;
        float lx = fmaxf(0.0f, fmaxf(1.0f - fabsf(dx1), 1.0f - fabsf(dx2)));
        float gy = __saturatef(dx1) * __saturatef(dx2);

        // row 0
        float dy1 = hf0 - r.p.z, dy2 = r.p.w - hf0;
        float gx = __saturatef(dy1) * __saturatef(dy2);
        float ly = fmaxf(0.0f, fmaxf(1.0f - fabsf(dy1), 1.0f - fabsf(dy2)));
        float xy0 = fmaxf(lx * gx, ly * gy);
        // row 1
        dy1 = hf1 - r.p.z; dy2 = r.p.w - hf1;
        gx = __saturatef(dy1) * __saturatef(dy2);
        ly = fmaxf(0.0f, fmaxf(1.0f - fabsf(dy1), 1.0f - fabsf(dy2)));
        float xy1 = fmaxf(lx * gx, ly * gy);

        u64 x0 = pk(xy0, xy0);
        u64 x1 = pk(xy1, xy1);
        float p0, p1;
        upk(p0, p1, pmul(x0, r.ca.x)); a0 = fmaxf(a0, p0); a1 = fmaxf(a1, p1);
        upk(p0, p1, pmul(x0, r.ca.y)); a2 = fmaxf(a2, p0); a3 = fmaxf(a3, p1);
        upk(p0, p1, pmul(x0, r.cb.x)); a4 = fmaxf(a4, p0); a5 = fmaxf(a5, p1);
        upk(p0, p1, pmul(x0, r.cb.y)); a6 = fmaxf(a6, p0); a7 = fmaxf(a7, p1);
        upk(p0, p1, pmul(x1, r.ca.x)); b0 = fmaxf(b0, p0); b1 = fmaxf(b1, p1);
        upk(p0, p1, pmul(x1, r.ca.y)); b2 = fmaxf(b2, p0); b3 = fmaxf(b3, p1);
        upk(p0, p1, pmul(x1, r.cb.x)); b4 = fmaxf(b4, p0); b5 = fmaxf(b5, p1);
        upk(p0, p1, pmul(x1, r.cb.y)); b6 = fmaxf(b6, p0); b7 = fmaxf(b7, p1);
    }

    float* o = out + (((size_t)b * NCLS) * Hd + h0) * Wd + tx;
    const int cs = Hd * Wd;
    o[0 * cs] = a0; o[1 * cs] = a1; o[2 * cs] = a2; o[3 * cs] = a3;
    o[4 * cs] = a4; o[5 * cs] = a5; o[6 * cs] = a6; o[7 * cs] = a7;
    o += Wd;
    o[0 * cs] = b0; o[1 * cs] = b1; o[2 * cs] = b2; o[3 * cs] = b3;
    o[4 * cs] = b4; o[5 * cs] = b5; o[6 * cs] = b6; o[7 * cs] = b7;
}

extern "C" void kernel_launch(void* const* d_in, const int* in_sizes, int n_in,
                              void* d_out, int out_size)
{
    const float* in = (const float*)d_in[0];
    float* out = (float*)d_out;
    int B = in_sizes[0] / (INCH * NUMB);   // 16

    prep_kernel<<<dim3(2, B), 1024>>>(in);
    layout_bbox_main<<<dim3(Hd / 4, B), dim3(128, 2)>>>(out);
}

// round 7
// speedup vs baseline: 1.2000x; 1.0656x over previous
#include <cuda_runtime.h>
#include <stdint.h>

// LayoutBBox: in (B,12,64) f32 -> out (B,8,128,128) f32
// out[b,c,h,w] = max_n xy[n,h,w]*cls[n,c], xy = max(lx(w)*gx(h), ly(h)*gy(w))
// prep: exact per-(b,w)/(b,h) nonzero bitmasks + packed box records (PDL producer)
// main: 2 rows/thread, union-mask visit loop, software-pipelined record loads,
//       128-thread CTAs, PDL consumer.

constexpr int Wd   = 128;
constexpr int Hd   = 128;
constexpr int NUMB = 64;
constexpr int NCLS = 8;
constexpr int INCH = 12;
constexpr int MAXB = 16;

using u64 = unsigned long long;

__device__ __forceinline__ u64 pk(float lo, float hi) {
    u64 r; asm("mov.b64 %0,{%1,%2};" : "=l"(r) : "f"(lo), "f"(hi)); return r;
}
__device__ __forceinline__ void upk(float& lo, float& hi, u64 v) {
    asm("mov.b64 {%0,%1},%2;" : "=f"(lo), "=f"(hi) : "l"(v));
}
__device__ __forceinline__ u64 pmul(u64 a, u64 b) {
    u64 r; asm("mul.rn.f32x2 %0,%1,%2;" : "=l"(r) : "l"(a), "l"(b)); return r;
}

struct __align__(16) Rec {              // 48 B per box
    float4     p;                       // x1, x2, y1, y2
    ulonglong2 ca;                      // packed (c0,c1),(c2,c3)
    ulonglong2 cb;                      // packed (c4,c5),(c6,c7)
};

__device__ ulonglong2 g_cmask[MAXB][Wd];   // (Mlx, Mgw) per (b,w)
__device__ ulonglong2 g_rmask[MAXB][Hd];   // (Mgh, Mly) per (b,h)
__device__ Rec        g_rec[MAXB][NUMB];

// ---------------- prep kernel: grid (2, B), block 1024 ----------------
__global__ void prep_kernel(const float* __restrict__ in)
{
    const int b   = blockIdx.y;
    const int tid = threadIdx.x;
    const float* base = in + (size_t)b * INCH * NUMB;

    if (blockIdx.x == 0) {
        if (tid < NUMB) {
            float xc = base[0 * NUMB + tid] * 128.0f;
            float yc = base[1 * NUMB + tid] * 128.0f;
            float bw = base[2 * NUMB + tid] * 128.0f;
            float bh = base[3 * NUMB + tid] * 128.0f;
            Rec r;
            r.p = make_float4(xc - 0.5f * bw, xc + 0.5f * bw,
                              yc - 0.5f * bh, yc + 0.5f * bh);
            r.ca.x = pk(base[4 * NUMB + tid],  base[5 * NUMB + tid]);
            r.ca.y = pk(base[6 * NUMB + tid],  base[7 * NUMB + tid]);
            r.cb.x = pk(base[8 * NUMB + tid],  base[9 * NUMB + tid]);
            r.cb.y = pk(base[10 * NUMB + tid], base[11 * NUMB + tid]);
            g_rec[b][tid] = r;
        }
        {   // column masks, byte-parallel
            int w = tid >> 3, j = tid & 7;
            float wf = (float)w;
            unsigned blx = 0, bgw = 0;
            #pragma unroll
            for (int k = 0; k < 8; k++) {
                int n = 8 * j + k;
                float xc = base[0 * NUMB + n] * 128.0f;
                float bw = base[2 * NUMB + n] * 128.0f;
                float x1 = xc - 0.5f * bw, x2 = xc + 0.5f * bw;
                if (fabsf(wf - x1) < 1.0f || fabsf(x2 - wf) < 1.0f) blx |= 1u << k;
                if (wf > x1 && wf < x2)                             bgw |= 1u << k;
            }
            unsigned char* dst = (unsigned char*)&g_cmask[b][w];
            dst[j]     = (unsigned char)blx;
            dst[8 + j] = (unsigned char)bgw;
        }
    } else {
        // row masks
        int h = tid >> 3, j = tid & 7;
        float hf = (float)h;
        unsigned bgh = 0, bly = 0;
        #pragma unroll
        for (int k = 0; k < 8; k++) {
            int n = 8 * j + k;
            float yc = base[1 * NUMB + n] * 128.0f;
            float bh = base[3 * NUMB + n] * 128.0f;
            float y1 = yc - 0.5f * bh, y2 = yc + 0.5f * bh;
            if (hf > y1 && hf < y2)                             bgh |= 1u << k;
            if (fabsf(hf - y1) < 1.0f || fabsf(y2 - hf) < 1.0f) bly |= 1u << k;
        }
        unsigned char* dst = (unsigned char*)&g_rmask[b][h];
        dst[j]     = (unsigned char)bgh;
        dst[8 + j] = (unsigned char)bly;
    }
    // PDL: our stores are done — let the dependent grid launch.
    asm volatile("griddepcontrol.launch_dependents;" ::: "memory");
}

// ---- per-box visit, both rows, accumulators by reference ----
__device__ __forceinline__ void visit(const Rec& r, float wf, float hf0, float hf1,
    float& a0, float& a1, float& a2, float& a3,
    float& a4, float& a5, float& a6, float& a7,
    float& b0, float& b1, float& b2, float& b3,
    float& b4, float& b5, float& b6, float& b7)
{
    float dx1 = wf - r.p.x, dx2 = r.p.y - wf;
    float lx = fmaxf(0.0f, fmaxf(1.0f - fabsf(dx1), 1.0f - fabsf(dx2)));
    float gy = __saturatef(dx1) * __saturatef(dx2);

    float dy1 = hf0 - r.p.z, dy2 = r.p.w - hf0;
    float gx = __saturatef(dy1) * __saturatef(dy2);
    float ly = fmaxf(0.0f, fmaxf(1.0f - fabsf(dy1), 1.0f - fabsf(dy2)));
    float xy0 = fmaxf(lx * gx, ly * gy);

    dy1 = hf1 - r.p.z; dy2 = r.p.w - hf1;
    gx = __saturatef(dy1) * __saturatef(dy2);
    ly = fmaxf(0.0f, fmaxf(1.0f - fabsf(dy1), 1.0f - fabsf(dy2)));
    float xy1 = fmaxf(lx * gx, ly * gy);

    u64 x0 = pk(xy0, xy0);
    u64 x1 = pk(xy1, xy1);
    float p0, p1;
    upk(p0, p1, pmul(x0, r.ca.x)); a0 = fmaxf(a0, p0); a1 = fmaxf(a1, p1);
    upk(p0, p1, pmul(x0, r.ca.y)); a2 = fmaxf(a2, p0); a3 = fmaxf(a3, p1);
    upk(p0, p1, pmul(x0, r.cb.x)); a4 = fmaxf(a4, p0); a5 = fmaxf(a5, p1);
    upk(p0, p1, pmul(x0, r.cb.y)); a6 = fmaxf(a6, p0); a7 = fmaxf(a7, p1);
    upk(p0, p1, pmul(x1, r.ca.x)); b0 = fmaxf(b0, p0); b1 = fmaxf(b1, p1);
    upk(p0, p1, pmul(x1, r.ca.y)); b2 = fmaxf(b2, p0); b3 = fmaxf(b3, p1);
    upk(p0, p1, pmul(x1, r.cb.x)); b4 = fmaxf(b4, p0); b5 = fmaxf(b5, p1);
    upk(p0, p1, pmul(x1, r.cb.y)); b6 = fmaxf(b6, p0); b7 = fmaxf(b7, p1);
}

// -------- main kernel: grid (Hd/2, B), block 128; 2 rows/thread --------
__global__ __launch_bounds__(128)
void layout_bbox_main(float* __restrict__ out)
{
    const int tx = threadIdx.x;                    // w
    const int b  = blockIdx.y;
    const int h0 = blockIdx.x * 2;                 // rows h0, h0+1
    const float wf  = (float)tx;
    const float hf0 = (float)h0;
    const float hf1 = hf0 + 1.0f;

    // PDL: wait for prep's global writes to be visible.
    asm volatile("griddepcontrol.wait;" ::: "memory");

    const Rec* __restrict__ rb = g_rec[b];
    const ulonglong2 cm  = g_cmask[b][tx];
    const ulonglong2 rm0 = g_rmask[b][h0];
    const ulonglong2 rm1 = g_rmask[b][h0 + 1];
    u64 m = (cm.x & (rm0.x | rm1.x)) | (cm.y & (rm0.y | rm1.y));

    float a0 = 0.f, a1 = 0.f, a2 = 0.f, a3 = 0.f;
    float a4 = 0.f, a5 = 0.f, a6 = 0.f, a7 = 0.f;
    float b0 = 0.f, b1 = 0.f, b2 = 0.f, b3 = 0.f;
    float b4 = 0.f, b5 = 0.f, b6 = 0.f, b7 = 0.f;

    if (m) {
        int n = __ffsll((long long)m) - 1;
        m &= m - 1;
        Rec r = rb[n];                             // 3x LDG.128
        while (m) {
            int n2 = __ffsll((long long)m) - 1;    // prefetch next record
            m &= m - 1;
            Rec r2 = rb[n2];
            visit(r, wf, hf0, hf1, a0,a1,a2,a3,a4,a5,a6,a7,
                                   b0,b1,b2,b3,b4,b5,b6,b7);
            r = r2;
        }
        visit(r, wf, hf0, hf1, a0,a1,a2,a3,a4,a5,a6,a7,
                               b0,b1,b2,b3,b4,b5,b6,b7);
    }

    float* o = out + (((size_t)b * NCLS) * Hd + h0) * Wd + tx;
    const int cs = Hd * Wd;
    o[0 * cs] = a0; o[1 * cs] = a1; o[2 * cs] = a2; o[3 * cs] = a3;
    o[4 * cs] = a4; o[5 * cs] = a5; o[6 * cs] = a6; o[7 * cs] = a7;
    o += Wd;
    o[0 * cs] = b0; o[1 * cs] = b1; o[2 * cs] = b2; o[3 * cs] = b3;
    o[4 * cs] = b4; o[5 * cs] = b5; o[6 * cs] = b6; o[7 * cs] = b7;
}

extern "C" void kernel_launch(void* const* d_in, const int* in_sizes, int n_in,
                              void* d_out, int out_size)
{
    const float* in = (const float*)d_in[0];
    float* out = (float*)d_out;
    int B = in_sizes[0] / (INCH * NUMB);   // 16

    prep_kernel<<<dim3(2, B), 1024>>>(in);

    // PDL launch of main: may start while prep is still resident.
    cudaLaunchConfig_t cfg = {};
    cfg.gridDim  = dim3(Hd / 2, B);        // (64, B) = 1024 CTAs
    cfg.blockDim = dim3(128);
    cudaLaunchAttribute attr[1];
    attr[0].id = cudaLaunchAttributeProgrammaticStreamSerialization;
    attr[0].val.programmaticStreamSerializationAllowed = 1;
    cfg.attrs = attr;
    cfg.numAttrs = 1;
    cudaLaunchKernelEx(&cfg, layout_bbox_main, out);
}